// round 14
// baseline (speedup 1.0000x reference)
#include <cuda_runtime.h>
#include <cstdint>

#define HH 128
#define NP 16384            // HH*HH pixels
#define GC 13               // color-grid cells per axis
#define NC (GC*GC*GC)       // 2197 cells
#define CELLW 21.0f
#define CAP 64              // max kept neighbors per pixel
#define ETH 16.0f           // keep K >= exp(-16); dropped tail ~2e-7
#define INV_TA (1.0f/160.0f)
#define INV_TB (1.0f/3.0f)
#define NBLK 128            // grid blocks (< 148 SMs -> co-resident)
#define NTHR 1024           // threads per block (32 warps)
#define SMT_BYTES (NP * 4)  // 64KB dynamic smem: full sm0 snapshot
// spatial Gaussian band: w(d) = exp(-d^2/18), support |d| <= 16 (w(16)~6.7e-7)

// ---------------- device scratch ----------------
__device__ int    g_cellCnt[NC];
__device__ int    g_cellStart[NC+1];
__device__ int    g_cursor[NC];
__device__ int    g_sidx[NP];
__device__ float4 g_sfA[NP];
__device__ float2 g_sfB[NP];
__device__ float2 g_ell[CAP*NP];     // slot-major: (.x=K, .y=bitcast idx)
__device__ int    g_ellCnt[NP];
__device__ float  g_blNorm[NP];
__device__ float  g_sm0[NP];         // single-buffered softmax ch0 (smem snapshots)
__device__ float  g_T[2*NP];         // double-buffered spatial row-pass
__device__ unsigned long long g_barCnt;

// ---- grid barrier: fence + atomic arrival, volatile-load polling ---------
__device__ __forceinline__ void gridbar(unsigned long long target) {
    __syncthreads();
    if (threadIdx.x == 0) {
        __threadfence();
        atomicAdd(&g_barCnt, 1ULL);
        volatile unsigned long long* c = &g_barCnt;
        while (*c < target) { }
        __threadfence();
    }
    __syncthreads();
}

__device__ __forceinline__ int clampCell(float v) {
    int c = (int)(v * (1.0f/CELLW));
    return c < 0 ? 0 : (c > GC-1 ? GC-1 : c);
}
__device__ __forceinline__ int cellOf(const float* __restrict__ rgb, int p) {
    return (clampCell(rgb[3*p+2])*GC + clampCell(rgb[3*p+1]))*GC + clampCell(rgb[3*p]);
}

__global__ void k_zero() {
    int t = blockIdx.x * blockDim.x + threadIdx.x;
    if (t == 0) g_barCnt = 0ULL;
    if (t < NC) g_cellCnt[t] = 0;
}

// ---------------- mega-kernel ----------------
__global__ void __launch_bounds__(NTHR, 1)
k_crf(const float* __restrict__ U, const float* __restrict__ rgb,
      const float* __restrict__ Ws, const float* __restrict__ Wb,
      const float* __restrict__ Cm, float* __restrict__ out) {
    extern __shared__ float smT[];              // 16384 floats: sm0 snapshot
    const int tid  = threadIdx.x;
    const int bid  = blockIdx.x;
    const int gtid = bid * NTHR + tid;          // 0..131071
    const int t    = tid & 127;
    const int qq   = tid >> 7;                  // eighth 0..7
    const int r    = bid;
    const int p    = r * HH + t;

    __shared__ float s[HH];
    __shared__ float red1[NTHR];
    __shared__ float red2[NTHR];
    __shared__ int   spart[256];

    // per-thread band weights: offsets d_i = qq*4 - 16 + i, i=0..3
    float wreg[4];
    #pragma unroll
    for (int i = 0; i < 4; i++) {
        int d = qq*4 - 16 + i;
        wreg[i] = __expf(-(float)(d*d) * (1.0f/18.0f));
    }

    // ---- phase A: per-cell counts ----
    if (gtid < NP) atomicAdd(&g_cellCnt[cellOf(rgb, gtid)], 1);
    gridbar(1ULL*NBLK);

    // ---- phase B: exclusive scan, parallel (block 0, uniform barriers) ----
    if (bid == 0) {
        const int CH = 9;           // 256*9 = 2304 >= 2197
        int base = tid*CH, sum = 0, loc[CH];
        if (tid < 256) {
            #pragma unroll
            for (int k = 0; k < CH; k++) {
                int c = base + k; int v = (c < NC) ? g_cellCnt[c] : 0;
                loc[k] = v; sum += v;
            }
            spart[tid] = sum;
        }
        __syncthreads();
        #pragma unroll
        for (int off = 1; off < 256; off <<= 1) {
            int addv = 0;
            if (tid < 256 && tid >= off) addv = spart[tid - off];
            __syncthreads();
            if (tid < 256) spart[tid] += addv;
            __syncthreads();
        }
        if (tid < 256) {
            int acc = (tid > 0) ? spart[tid - 1] : 0;   // exclusive base
            #pragma unroll
            for (int k = 0; k < CH; k++) {
                int c = base + k;
                if (c < NC) { g_cellStart[c] = acc; g_cursor[c] = acc; }
                acc += loc[k];
            }
        }
        if (tid == 255) g_cellStart[NC] = spart[255];
    }
    gridbar(2ULL*NBLK);

    // ---- phase C: scatter pixel ids ----
    if (gtid < NP) {
        int slot = atomicAdd(&g_cursor[cellOf(rgb, gtid)], 1);
        g_sidx[slot] = gtid;
    }
    gridbar(3ULL*NBLK);

    // ---- phase D: warp-per-cell rank sort + feature fill (fused) ----------
    {
        int w = gtid >> 5;
        int lane = tid & 31;
        if (w < NC) {
            int st = g_cellStart[w], en = g_cellStart[w+1];
            int n = en - st;
            if (n <= 32) {
                int v = (lane < n) ? g_sidx[st + lane] : 0x7FFFFFFF;
                int rank = 0;
                #pragma unroll
                for (int j = 0; j < 32; j++) {
                    int u = __shfl_sync(0xffffffffu, v, j);
                    rank += (u < v) ? 1 : 0;
                }
                if (lane < n) {
                    int sl = st + rank;
                    int y = v >> 7, x = v & 127;
                    g_sfA[sl] = make_float4((float)x * INV_TA, (float)y * INV_TA,
                                            rgb[3*v] * INV_TB, rgb[3*v+1] * INV_TB);
                    g_sfB[sl] = make_float2(rgb[3*v+2] * INV_TB, __int_as_float(v));
                }
            } else {
                if (lane == 0) {
                    for (int a = st + 1; a < en; a++) {
                        int v = g_sidx[a]; int k = a - 1;
                        while (k >= st && g_sidx[k] > v) { g_sidx[k+1] = g_sidx[k]; k--; }
                        g_sidx[k+1] = v;
                    }
                }
                __syncwarp();
                for (int sl = st + lane; sl < en; sl += 32) {
                    int v = g_sidx[sl];
                    int y = v >> 7, x = v & 127;
                    g_sfA[sl] = make_float4((float)x * INV_TA, (float)y * INV_TA,
                                            rgb[3*v] * INV_TB, rgb[3*v+1] * INV_TB);
                    g_sfB[sl] = make_float2(rgb[3*v+2] * INV_TB, __int_as_float(v));
                }
            }
        }
    }
    gridbar(4ULL*NBLK);

    // ---- phase E: ELL build, warp per pixel (4096 warps x 4 pixels) --------
    {
        int gwarp = (gtid >> 5);
        int lane  = tid & 31;
        for (int i = 0; i < 4; i++) {
            int pp = gwarp * 4 + i;
            int y = pp >> 7, x = pp & 127;
            float f0 = (float)x * INV_TA;
            float f1 = (float)y * INV_TA;
            float f2 = rgb[3*pp]   * INV_TB;
            float f3 = rgb[3*pp+1] * INV_TB;
            float f4 = rgb[3*pp+2] * INV_TB;
            int c0 = clampCell(rgb[3*pp]);
            int c1 = clampCell(rgb[3*pp+1]);
            int c2 = clampCell(rgb[3*pp+2]);
            int xlo = c0 > 0      ? c0 - 1 : 0;
            int xhi = c0 < GC - 1 ? c0 + 1 : GC - 1;

            int stA[9], enA[9];
            #pragma unroll
            for (int rr = 0; rr < 9; rr++) {
                int dz = rr / 3 - 1, dy = rr % 3 - 1;
                int cz = c2 + dz, cy = c1 + dy;
                bool ok = (cz >= 0) && (cz < GC) && (cy >= 0) && (cy < GC);
                int base = ok ? (cz*GC + cy)*GC : 0;
                int lo = ok ? g_cellStart[base + xlo]     : 0;
                int hi = ok ? g_cellStart[base + xhi + 1] : 0;
                stA[rr] = lo; enA[rr] = hi;
            }

            int cnt = 0; float norm = 0.0f;
            #pragma unroll
            for (int rr = 0; rr < 9; rr++) {
                for (int s0 = stA[rr]; s0 < enA[rr]; s0 += 32) {
                    int sl = s0 + lane;
                    bool keep = false; float val = 0.0f; int jdx = 0;
                    if (sl < enA[rr]) {
                        float4 fA = g_sfA[sl];
                        float2 fB = g_sfB[sl];
                        float d0 = f0-fA.x, d1 = f1-fA.y, d2 = f2-fA.z,
                              d3 = f3-fA.w, d4 = f4-fB.x;
                        float e = 0.5f*(d0*d0+d1*d1+d2*d2+d3*d3+d4*d4);
                        if (e < ETH) { keep = true; val = __expf(-e);
                                       jdx = __float_as_int(fB.y); }
                    }
                    unsigned m = __ballot_sync(0xffffffffu, keep);
                    if (keep) {
                        int off = cnt + __popc(m & ((1u << lane) - 1u));
                        if (off < CAP) {
                            g_ell[off*NP + pp] = make_float2(val, __int_as_float(jdx));
                            norm += val;
                        }
                    }
                    cnt += __popc(m);
                }
            }
            if (cnt > CAP) cnt = CAP;
            for (int o = 16; o > 0; o >>= 1)
                norm += __shfl_xor_sync(0xffffffffu, norm, o);
            if (lane == 0) { g_ellCnt[pp] = cnt; g_blNorm[pp] = norm; }
        }
    }
    gridbar(5ULL*NBLK);

    // ---- hoist ELL row slots into registers (8 per thread) ----
    float evv[8]; int evi[8];
    {
        int cnt = g_ellCnt[p];
        #pragma unroll
        for (int i = 0; i < 8; i++) {
            int k = qq + 8*i;
            float2 e = (k < cnt) ? g_ell[k*NP + p] : make_float2(0.0f, __int_as_float(0));
            evv[i] = e.x; evi[i] = __float_as_int(e.y);
        }
    }

    // ---- prologue: constants + sm(U) + band row pass into T buffer 0 ----
    float u0 = 0.f, u1 = 0.f, invn = 0.f, bln = 1.f;
    if (tid < HH) {
        float rsr = 0.f, rst = 0.f;
        #pragma unroll
        for (int d = -16; d < 16; d++) {
            float w = __expf(-(float)(d*d) * (1.0f/18.0f));
            if ((unsigned)(r + d) < (unsigned)HH) rsr += w;
            if ((unsigned)(t + d) < (unsigned)HH) rst += w;
        }
        invn = 1.0f / (rsr * rst);
        bln  = g_blNorm[p];
        u0 = U[2*p]; u1 = U[2*p+1];
        float sm = 1.0f / (1.0f + __expf(u1 - u0));
        g_sm0[p] = sm;
        s[t] = sm;
    }
    float ws0 = Ws[0], ws1 = Ws[1], ws2 = Ws[2], ws3 = Ws[3];
    float wb0 = Wb[0], wb1 = Wb[1], wb2 = Wb[2], wb3 = Wb[3];
    float cm0 = Cm[0], cm1 = Cm[1], cm2 = Cm[2], cm3 = Cm[3];
    __syncthreads();
    {   // band row pass: eighth qq does 4 taps
        float acc = 0.0f;
        #pragma unroll
        for (int i = 0; i < 4; i++) {
            int k = t + qq*4 - 16 + i;
            if ((unsigned)k < (unsigned)HH) acc += s[k] * wreg[i];
        }
        red1[tid] = acc;
        __syncthreads();
        if (tid < HH) {
            float a = 0.0f;
            #pragma unroll
            for (int j = 0; j < 8; j++) a += red1[t + 128*j];
            g_T[p] = a;
        }
    }
    gridbar(6ULL*NBLK);

    // ---- 10 mean-field iterations ----
    float q0 = u0, q1 = u1;
    for (int it = 0; it < 10; it++) {
        int cur = it & 1, nxt = cur ^ 1;

        // copy global sm0 snapshot into smem (coalesced, 4 float4/thread)
        {
            const float4* src = reinterpret_cast<const float4*>(g_sm0);
            float4* dst = reinterpret_cast<float4*>(smT);
            #pragma unroll
            for (int i = 0; i < 4; i++)
                dst[tid + NTHR*i] = src[tid + NTHR*i];
        }
        __syncthreads();

        // band column pass partial (4 independent global loads per thread)
        {
            const float* Tc = g_T + cur*NP;
            float acc = 0.0f;
            #pragma unroll
            for (int i = 0; i < 4; i++) {
                int j = r + qq*4 - 16 + i;
                if ((unsigned)j < (unsigned)HH) acc += wreg[i] * Tc[j*HH + t];
            }
            red1[tid] = acc;
        }
        // bilateral SpMV partial: 8 LDS gathers from smem snapshot
        {
            float acc = 0.0f;
            #pragma unroll
            for (int i = 0; i < 8; i++)
                acc += evv[i] * smT[evi[i]];
            red2[tid] = acc;
        }
        __syncthreads();

        if (tid < HH) {
            float sp = 0.0f, bl = 0.0f;
            #pragma unroll
            for (int j = 0; j < 8; j++) {
                sp += red1[t + 128*j];
                bl += red2[t + 128*j];
            }
            sp *= invn;
            bl /= bln;
            float sp1 = 1.0f - sp, bl1 = 1.0f - bl;
            float mp0 = ws0*sp + ws1*sp1 + wb0*bl + wb1*bl1;
            float mp1 = ws2*sp + ws3*sp1 + wb2*bl + wb3*bl1;
            q0 = u0 - (cm0*mp0 + cm1*mp1);
            q1 = u1 - (cm2*mp0 + cm3*mp1);
            if (it < 9) {
                float sm = 1.0f / (1.0f + __expf(q1 - q0));
                g_sm0[p] = sm;          // single buffer: copies happen post-barrier
                s[t] = sm;
            }
        }
        if (it < 9) {
            __syncthreads();
            float acc = 0.0f;
            #pragma unroll
            for (int i = 0; i < 4; i++) {
                int k = t + qq*4 - 16 + i;
                if ((unsigned)k < (unsigned)HH) acc += s[k] * wreg[i];
            }
            red1[tid] = acc;
            __syncthreads();
            if (tid < HH) {
                float a = 0.0f;
                #pragma unroll
                for (int j = 0; j < 8; j++) a += red1[t + 128*j];
                g_T[nxt*NP + p] = a;
            }
            gridbar((unsigned long long)(7 + it) * NBLK);
        }
    }

    if (tid < HH) {
        out[2*p]   = q0;
        out[2*p+1] = q1;
    }
}

// ---------------- launch ----------------
extern "C" void kernel_launch(void* const* d_in, const int* in_sizes, int n_in,
                              void* d_out, int out_size) {
    const float* U   = (const float*)d_in[0];
    const float* rgb = (const float*)d_in[1];
    const float* Ws  = (const float*)d_in[2];
    const float* Wb  = (const float*)d_in[3];
    const float* Cm  = (const float*)d_in[4];
    float* out = (float*)d_out;

    cudaFuncSetAttribute(k_crf, cudaFuncAttributeMaxDynamicSharedMemorySize,
                         SMT_BYTES);

    k_zero<<<(NC + 511)/512, 512>>>();
    k_crf <<<NBLK, NTHR, SMT_BYTES>>>(U, rgb, Ws, Wb, Cm, out);
}

// round 15
// speedup vs baseline: 1.1186x; 1.1186x over previous
#include <cuda_runtime.h>
#include <cstdint>

#define HH 128
#define NP 16384            // HH*HH pixels
#define GC 13               // color-grid cells per axis
#define NC (GC*GC*GC)       // 2197 cells
#define CELLW 21.0f
#define CAP 64              // max kept neighbors per pixel
#define CAPP 65             // padded row stride (bank-conflict avoidance)
#define ETH 16.0f           // keep K >= exp(-16); dropped tail ~2e-7
#define INV_TA (1.0f/160.0f)
#define INV_TB (1.0f/3.0f)
#define NBLK 128            // grid blocks (< 148 SMs -> co-resident)
#define NTHR 1024           // threads per block (32 warps)
#define SMELL_BYTES (128 * CAPP * 8)   // 66560B dynamic smem: block-local ELL
// spatial Gaussian band: w(d) = exp(-d^2/18), support |d| <= 16 (w(16)~6.7e-7)

// ---------------- device scratch ----------------
__device__ int    g_cellCnt[NC];
__device__ int    g_cellStart[NC+1];
__device__ int    g_cursor[NC];
__device__ int    g_sidx[NP];
__device__ float4 g_sfA[NP];
__device__ float2 g_sfB[NP];
__device__ float  g_sm0[2*NP];       // double-buffered softmax ch0
__device__ float  g_T[2*NP];         // double-buffered spatial row-pass
__device__ unsigned long long g_barCnt;

// ---- grid barrier: fence + atomic arrival, volatile-load polling ---------
__device__ __forceinline__ void gridbar(unsigned long long target) {
    __syncthreads();
    if (threadIdx.x == 0) {
        __threadfence();
        atomicAdd(&g_barCnt, 1ULL);
        volatile unsigned long long* c = &g_barCnt;
        while (*c < target) { }
        __threadfence();
    }
    __syncthreads();
}

__device__ __forceinline__ int clampCell(float v) {
    int c = (int)(v * (1.0f/CELLW));
    return c < 0 ? 0 : (c > GC-1 ? GC-1 : c);
}
__device__ __forceinline__ int cellOf(const float* __restrict__ rgb, int p) {
    return (clampCell(rgb[3*p+2])*GC + clampCell(rgb[3*p+1]))*GC + clampCell(rgb[3*p]);
}

__global__ void k_zero() {
    int t = blockIdx.x * blockDim.x + threadIdx.x;
    if (t == 0) g_barCnt = 0ULL;
    if (t < NC) g_cellCnt[t] = 0;
}

// ---------------- mega-kernel ----------------
__global__ void __launch_bounds__(NTHR, 1)
k_crf(const float* __restrict__ U, const float* __restrict__ rgb,
      const float* __restrict__ Ws, const float* __restrict__ Wb,
      const float* __restrict__ Cm, float* __restrict__ out) {
    extern __shared__ char smraw[];
    float2* smEll = reinterpret_cast<float2*>(smraw);   // [128][CAPP]
    const int tid  = threadIdx.x;
    const int bid  = blockIdx.x;
    const int gtid = bid * NTHR + tid;
    const int t    = tid & 127;
    const int qq   = tid >> 7;                  // eighth 0..7
    const int r    = bid;
    const int p    = r * HH + t;

    __shared__ float s[HH];
    __shared__ float red1[NTHR];
    __shared__ float red2[NTHR];
    __shared__ int   spart[256];
    __shared__ int   sCnt[HH];
    __shared__ float sNorm[HH];

    // per-thread band weights: offsets d_i = qq*4 - 16 + i, i=0..3
    float wreg[4];
    #pragma unroll
    for (int i = 0; i < 4; i++) {
        int d = qq*4 - 16 + i;
        wreg[i] = __expf(-(float)(d*d) * (1.0f/18.0f));
    }

    // ---- phase A: per-cell counts ----
    if (gtid < NP) atomicAdd(&g_cellCnt[cellOf(rgb, gtid)], 1);
    gridbar(1ULL*NBLK);

    // ---- phase B: exclusive scan, parallel (block 0, uniform barriers) ----
    if (bid == 0) {
        const int CH = 9;           // 256*9 = 2304 >= 2197
        int base = tid*CH, sum = 0, loc[CH];
        if (tid < 256) {
            #pragma unroll
            for (int k = 0; k < CH; k++) {
                int c = base + k; int v = (c < NC) ? g_cellCnt[c] : 0;
                loc[k] = v; sum += v;
            }
            spart[tid] = sum;
        }
        __syncthreads();
        #pragma unroll
        for (int off = 1; off < 256; off <<= 1) {
            int addv = 0;
            if (tid < 256 && tid >= off) addv = spart[tid - off];
            __syncthreads();
            if (tid < 256) spart[tid] += addv;
            __syncthreads();
        }
        if (tid < 256) {
            int acc = (tid > 0) ? spart[tid - 1] : 0;
            #pragma unroll
            for (int k = 0; k < CH; k++) {
                int c = base + k;
                if (c < NC) { g_cellStart[c] = acc; g_cursor[c] = acc; }
                acc += loc[k];
            }
        }
        if (tid == 255) g_cellStart[NC] = spart[255];
    }
    gridbar(2ULL*NBLK);

    // ---- phase C: scatter pixel ids ----
    if (gtid < NP) {
        int slot = atomicAdd(&g_cursor[cellOf(rgb, gtid)], 1);
        g_sidx[slot] = gtid;
    }
    gridbar(3ULL*NBLK);

    // ---- phase D: warp-per-cell rank sort + feature fill (fused) ----------
    {
        int w = gtid >> 5;
        int lane = tid & 31;
        if (w < NC) {
            int st = g_cellStart[w], en = g_cellStart[w+1];
            int n = en - st;
            if (n <= 32) {
                int v = (lane < n) ? g_sidx[st + lane] : 0x7FFFFFFF;
                int rank = 0;
                #pragma unroll
                for (int j = 0; j < 32; j++) {
                    int u = __shfl_sync(0xffffffffu, v, j);
                    rank += (u < v) ? 1 : 0;
                }
                if (lane < n) {
                    int sl = st + rank;
                    int y = v >> 7, x = v & 127;
                    g_sfA[sl] = make_float4((float)x * INV_TA, (float)y * INV_TA,
                                            rgb[3*v] * INV_TB, rgb[3*v+1] * INV_TB);
                    g_sfB[sl] = make_float2(rgb[3*v+2] * INV_TB, __int_as_float(v));
                }
            } else {
                if (lane == 0) {
                    for (int a = st + 1; a < en; a++) {
                        int v = g_sidx[a]; int k = a - 1;
                        while (k >= st && g_sidx[k] > v) { g_sidx[k+1] = g_sidx[k]; k--; }
                        g_sidx[k+1] = v;
                    }
                }
                __syncwarp();
                for (int sl = st + lane; sl < en; sl += 32) {
                    int v = g_sidx[sl];
                    int y = v >> 7, x = v & 127;
                    g_sfA[sl] = make_float4((float)x * INV_TA, (float)y * INV_TA,
                                            rgb[3*v] * INV_TB, rgb[3*v+1] * INV_TB);
                    g_sfB[sl] = make_float2(rgb[3*v+2] * INV_TB, __int_as_float(v));
                }
            }
        }
    }
    gridbar(4ULL*NBLK);

    // ---- phase E: ELL build into SMEM, warp per pixel, MLP-3 groups -------
    {
        int warp = tid >> 5;                    // 0..31 (block-local)
        int lane = tid & 31;
        unsigned lmask = (1u << lane) - 1u;
        for (int i = 0; i < 4; i++) {
            int lp = warp * 4 + i;              // local pixel 0..127
            int pp = bid * 128 + lp;            // global pixel (this block's row)
            int y = pp >> 7, x = pp & 127;
            float f0 = (float)x * INV_TA;
            float f1 = (float)y * INV_TA;
            float f2 = rgb[3*pp]   * INV_TB;
            float f3 = rgb[3*pp+1] * INV_TB;
            float f4 = rgb[3*pp+2] * INV_TB;
            int c0 = clampCell(rgb[3*pp]);
            int c1 = clampCell(rgb[3*pp+1]);
            int c2 = clampCell(rgb[3*pp+2]);
            int xlo = c0 > 0      ? c0 - 1 : 0;
            int xhi = c0 < GC - 1 ? c0 + 1 : GC - 1;

            // prefetch all 9 (st,en) range bounds with full MLP
            int stA[9], enA[9];
            #pragma unroll
            for (int rr = 0; rr < 9; rr++) {
                int dz = rr / 3 - 1, dy = rr % 3 - 1;
                int cz = c2 + dz, cy = c1 + dy;
                bool ok = (cz >= 0) && (cz < GC) && (cy >= 0) && (cy < GC);
                int base = ok ? (cz*GC + cy)*GC : 0;
                int lo = ok ? g_cellStart[base + xlo]     : 0;
                int hi = ok ? g_cellStart[base + xhi + 1] : 0;
                stA[rr] = lo; enA[rr] = hi;
            }

            int cnt = 0; float norm = 0.0f;
            #pragma unroll
            for (int g = 0; g < 3; g++) {
                // batch-load first round of 3 ranges (independent -> MLP=3)
                float4 fa[3]; float2 fb[3]; bool vq[3];
                #pragma unroll
                for (int k = 0; k < 3; k++) {
                    int rr = g*3 + k;
                    vq[k] = (stA[rr] + lane) < enA[rr];
                    fa[k] = make_float4(0,0,0,0);
                    fb[k] = make_float2(0,0);
                    if (vq[k]) {
                        int sl = stA[rr] + lane;
                        fa[k] = g_sfA[sl]; fb[k] = g_sfB[sl];
                    }
                }
                #pragma unroll
                for (int k = 0; k < 3; k++) {
                    int rr = g*3 + k;
                    // process first round
                    {
                        bool keep = false; float val = 0.0f; int jdx = 0;
                        if (vq[k]) {
                            float d0 = f0-fa[k].x, d1 = f1-fa[k].y, d2 = f2-fa[k].z,
                                  d3 = f3-fa[k].w, d4 = f4-fb[k].x;
                            float e = 0.5f*(d0*d0+d1*d1+d2*d2+d3*d3+d4*d4);
                            if (e < ETH) { keep = true; val = __expf(-e);
                                           jdx = __float_as_int(fb[k].y); }
                        }
                        unsigned m = __ballot_sync(0xffffffffu, keep);
                        if (keep) {
                            int off = cnt + __popc(m & lmask);
                            if (off < CAP) {
                                smEll[lp*CAPP + off] = make_float2(val, __int_as_float(jdx));
                                norm += val;
                            }
                        }
                        cnt += __popc(m);
                    }
                    // overflow rounds (range longer than 32; rare)
                    for (int s0 = stA[rr] + 32; s0 < enA[rr]; s0 += 32) {
                        int sl = s0 + lane;
                        bool keep = false; float val = 0.0f; int jdx = 0;
                        if (sl < enA[rr]) {
                            float4 fA = g_sfA[sl];
                            float2 fB = g_sfB[sl];
                            float d0 = f0-fA.x, d1 = f1-fA.y, d2 = f2-fA.z,
                                  d3 = f3-fA.w, d4 = f4-fB.x;
                            float e = 0.5f*(d0*d0+d1*d1+d2*d2+d3*d3+d4*d4);
                            if (e < ETH) { keep = true; val = __expf(-e);
                                           jdx = __float_as_int(fB.y); }
                        }
                        unsigned m = __ballot_sync(0xffffffffu, keep);
                        if (keep) {
                            int off = cnt + __popc(m & lmask);
                            if (off < CAP) {
                                smEll[lp*CAPP + off] = make_float2(val, __int_as_float(jdx));
                                norm += val;
                            }
                        }
                        cnt += __popc(m);
                    }
                }
            }
            if (cnt > CAP) cnt = CAP;
            for (int o = 16; o > 0; o >>= 1)
                norm += __shfl_xor_sync(0xffffffffu, norm, o);
            if (lane == 0) { sCnt[lp] = cnt; sNorm[lp] = norm; }
        }
    }
    __syncthreads();   // ELL is block-local: no grid barrier needed

    // ---- hoist ELL row slots into registers (8 per thread, from smem) ----
    float evv[8]; int evi[8];
    {
        int cnt = sCnt[t];
        #pragma unroll
        for (int i = 0; i < 8; i++) {
            int k = qq + 8*i;
            float2 e = (k < cnt) ? smEll[t*CAPP + k]
                                 : make_float2(0.0f, __int_as_float(0));
            evv[i] = e.x; evi[i] = __float_as_int(e.y);
        }
    }

    // ---- prologue: constants + sm(U) + band row pass into T buffer 0 ----
    float u0 = 0.f, u1 = 0.f, invn = 0.f, bln = 1.f;
    if (tid < HH) {
        float rsr = 0.f, rst = 0.f;
        #pragma unroll
        for (int d = -16; d < 16; d++) {
            float w = __expf(-(float)(d*d) * (1.0f/18.0f));
            if ((unsigned)(r + d) < (unsigned)HH) rsr += w;
            if ((unsigned)(t + d) < (unsigned)HH) rst += w;
        }
        invn = 1.0f / (rsr * rst);
        bln  = sNorm[t];
        u0 = U[2*p]; u1 = U[2*p+1];
        float sm = 1.0f / (1.0f + __expf(u1 - u0));
        g_sm0[p] = sm;
        s[t] = sm;
    }
    float ws0 = Ws[0], ws1 = Ws[1], ws2 = Ws[2], ws3 = Ws[3];
    float wb0 = Wb[0], wb1 = Wb[1], wb2 = Wb[2], wb3 = Wb[3];
    float cm0 = Cm[0], cm1 = Cm[1], cm2 = Cm[2], cm3 = Cm[3];
    __syncthreads();
    {   // band row pass: eighth qq does 4 taps
        float acc = 0.0f;
        #pragma unroll
        for (int i = 0; i < 4; i++) {
            int k = t + qq*4 - 16 + i;
            if ((unsigned)k < (unsigned)HH) acc += s[k] * wreg[i];
        }
        red1[tid] = acc;
        __syncthreads();
        if (tid < HH) {
            float a = 0.0f;
            #pragma unroll
            for (int j = 0; j < 8; j++) a += red1[t + 128*j];
            g_T[p] = a;
        }
    }
    gridbar(5ULL*NBLK);

    // ---- 10 mean-field iterations ----
    float q0 = u0, q1 = u1;
    for (int it = 0; it < 10; it++) {
        int cur = it & 1, nxt = cur ^ 1;

        // band column pass partial (4 independent loads per thread)
        {
            const float* Tc = g_T + cur*NP;
            float acc = 0.0f;
            #pragma unroll
            for (int i = 0; i < 4; i++) {
                int j = r + qq*4 - 16 + i;
                if ((unsigned)j < (unsigned)HH) acc += wreg[i] * Tc[j*HH + t];
            }
            red1[tid] = acc;
        }
        // bilateral SpMV partial: 8 independent gathers (ELL in registers)
        {
            const float* smc = g_sm0 + cur*NP;
            float acc = 0.0f;
            #pragma unroll
            for (int i = 0; i < 8; i++)
                acc += evv[i] * smc[evi[i]];
            red2[tid] = acc;
        }
        __syncthreads();

        if (tid < HH) {
            float sp = 0.0f, bl = 0.0f;
            #pragma unroll
            for (int j = 0; j < 8; j++) {
                sp += red1[t + 128*j];
                bl += red2[t + 128*j];
            }
            sp *= invn;
            bl /= bln;
            float sp1 = 1.0f - sp, bl1 = 1.0f - bl;
            float mp0 = ws0*sp + ws1*sp1 + wb0*bl + wb1*bl1;
            float mp1 = ws2*sp + ws3*sp1 + wb2*bl + wb3*bl1;
            q0 = u0 - (cm0*mp0 + cm1*mp1);
            q1 = u1 - (cm2*mp0 + cm3*mp1);
            if (it < 9) {
                float sm = 1.0f / (1.0f + __expf(q1 - q0));
                g_sm0[nxt*NP + p] = sm;
                s[t] = sm;
            }
        }
        if (it < 9) {
            __syncthreads();
            float acc = 0.0f;
            #pragma unroll
            for (int i = 0; i < 4; i++) {
                int k = t + qq*4 - 16 + i;
                if ((unsigned)k < (unsigned)HH) acc += s[k] * wreg[i];
            }
            red1[tid] = acc;
            __syncthreads();
            if (tid < HH) {
                float a = 0.0f;
                #pragma unroll
                for (int j = 0; j < 8; j++) a += red1[t + 128*j];
                g_T[nxt*NP + p] = a;
            }
            gridbar((unsigned long long)(6 + it) * NBLK);
        }
    }

    if (tid < HH) {
        out[2*p]   = q0;
        out[2*p+1] = q1;
    }
}

// ---------------- launch ----------------
extern "C" void kernel_launch(void* const* d_in, const int* in_sizes, int n_in,
                              void* d_out, int out_size) {
    const float* U   = (const float*)d_in[0];
    const float* rgb = (const float*)d_in[1];
    const float* Ws  = (const float*)d_in[2];
    const float* Wb  = (const float*)d_in[3];
    const float* Cm  = (const float*)d_in[4];
    float* out = (float*)d_out;

    cudaFuncSetAttribute(k_crf, cudaFuncAttributeMaxDynamicSharedMemorySize,
                         SMELL_BYTES);

    k_zero<<<(NC + 511)/512, 512>>>();
    k_crf <<<NBLK, NTHR, SMELL_BYTES>>>(U, rgb, Ws, Wb, Cm, out);
}